// round 12
// baseline (speedup 1.0000x reference)
#include <cuda_runtime.h>
#include <cuda.h>
#include <cuda_fp16.h>
#include <cuda_fp8.h>
#include <cstdint>

#define BATCH 512
#define SEQLEN 512
#define INSZ 64
#define RES 1024
#define OUTSZ 64

// ---------------- static device buffers (no allocation allowed) -------------
__device__ float g_state[BATCH * RES];              // fp32 state, in-place
__device__ __half g_shi[2][BATCH * RES];            // state hi (fp16), ping-pong
__device__ unsigned char g_slo8[2][BATCH * RES];    // state lo (e4m3 * 2^12)
__device__ __half g_w16[RES * RES];                 // W_res fp16 [k][n]
__device__ unsigned char g_w8T[RES * RES];          // e4m3(W*16) [n][k]
__device__ __half g_win16[INSZ * RES];              // W_in fp16
__device__ __half g_xhi[BATCH * SEQLEN * INSZ];     // input hi
__device__ __half g_xlo[BATCH * SEQLEN * INSZ];     // input lo (fp16)

struct TMaps {
    CUtensorMap shi[2];
    CUtensorMap slo8[2];
    CUtensorMap w;
    CUtensorMap w8T;
    CUtensorMap win;
    CUtensorMap xhi;
    CUtensorMap xlo;
};

// ---------------- prep kernels ----------------------------------------------
__global__ void prep_kernel(const float* __restrict__ input,
                            const float* __restrict__ Wres,
                            const float* __restrict__ Win) {
    int i = blockIdx.x * blockDim.x + threadIdx.x;
    int stride = gridDim.x * blockDim.x;
    const __half z = __float2half(0.0f);
    for (int k = i; k < BATCH * SEQLEN * INSZ; k += stride) {
        float v = input[k];
        __half h = __float2half(v);
        g_xhi[k] = h;
        g_xlo[k] = __float2half(v - __half2float(h));
        if (k < RES * RES) g_w16[k] = __float2half(Wres[k]);
        if (k < INSZ * RES) g_win16[k] = __float2half(Win[k]);
        if (k < BATCH * RES) {
            g_state[k] = 0.0f;
            g_shi[0][k] = z;
            g_slo8[0][k] = 0;
        }
    }
}

// W [k][n] fp32 -> g_w8T [n][k] = e4m3(W*16)
__global__ void w8t_kernel(const float* __restrict__ W) {
    __shared__ float tile[32][33];
    int k0 = blockIdx.x * 32, n0 = blockIdx.y * 32;
    int tx = threadIdx.x, ty = threadIdx.y;            // 32 x 8
    #pragma unroll
    for (int j = 0; j < 32; j += 8)
        tile[ty + j][tx] = W[(size_t)(k0 + ty + j) * RES + n0 + tx];
    __syncthreads();
    #pragma unroll
    for (int j = 0; j < 32; j += 8) {
        float v = tile[tx][ty + j] * 16.0f;            // W[k0+tx][n0+ty+j]
        g_w8T[(size_t)(n0 + ty + j) * RES + k0 + tx] =
            __nv_cvt_float_to_fp8(v, __NV_SATFINITE, __NV_E4M3);
    }
}

// ---------------- fast tanh (ex2 + rcp approx; abs err ~1e-6) ---------------
__device__ __forceinline__ float fast_tanhf(float x) {
    float e;
    asm("ex2.approx.f32 %0, %1;" : "=f"(e) : "f"(x * 2.8853900817779268f));
    float r;
    asm("rcp.approx.f32 %0, %1;" : "=f"(r) : "f"(e + 1.0f));
    return fmaf(-2.0f, r, 1.0f);
}

// ---------------- PTX helpers ------------------------------------------------
#define MBARRIER_INIT(addr, cnt) \
    asm volatile("mbarrier.init.shared.b64 [%0], %1;" :: "r"(addr), "r"(cnt) : "memory")

#define MBARRIER_EXPECT_TX(addr, bytes) \
    asm volatile("mbarrier.arrive.expect_tx.shared.b64 _, [%0], %1;" \
                 :: "r"(addr), "r"(bytes) : "memory")

#define MBARRIER_WAIT_PARITY(mbar, par) do {                                   \
    uint32_t _m = (mbar); uint32_t _p = (par); uint32_t _done;                 \
    asm volatile("{\n\t.reg .pred p;\n\t"                                      \
        "mbarrier.try_wait.parity.acquire.cta.shared::cta.b64 p, [%1], %2;\n\t"\
        "selp.b32 %0, 1, 0, p;\n\t}" : "=r"(_done) : "r"(_m), "r"(_p) : "memory"); \
    if (!_done) {                                                              \
        asm volatile("{\n\t.reg .pred P1;\n\tWL_%=:\n\t"                       \
            "mbarrier.try_wait.parity.acquire.cta.shared::cta.b64 P1, [%0], %1, 0x989680;\n\t" \
            "@P1 bra.uni WD_%=;\n\tbra.uni WL_%=;\n\tWD_%=:\n\t}"              \
            :: "r"(_m), "r"(_p) : "memory");                                   \
    }                                                                          \
} while (0)

__device__ __forceinline__ void tma2d(uint32_t dst, const CUtensorMap* m,
                                      int c0, int c1, uint32_t mbar) {
    asm volatile(
        "cp.async.bulk.tensor.2d.shared::cluster.global.tile.mbarrier::complete_tx::bytes "
        "[%0], [%1, {%2, %3}], [%4];"
        :: "r"(dst), "l"(m), "r"(c0), "r"(c1), "r"(mbar) : "memory");
}

__device__ __forceinline__ void tma3d(uint32_t dst, const CUtensorMap* m,
                                      int c0, int c1, int c2, uint32_t mbar) {
    asm volatile(
        "cp.async.bulk.tensor.3d.shared::cluster.global.tile.mbarrier::complete_tx::bytes "
        "[%0], [%1, {%2, %3, %4}], [%5];"
        :: "r"(dst), "l"(m), "r"(c0), "r"(c1), "r"(c2), "r"(mbar) : "memory");
}

// ---------------- step kernel ----------------------------------------------
// Y = Shi@W16 (fp16 mma) + 2^-16 * Slo8@W8T (fp8 mma) + input proj (fp16).
// 9 K-blocks (8 x BK128 state/W + 1 x BK64 input). TMA loader, 3-slot ring.
// 256 threads (8 warps, 4Mx2N, warp tile 16x32). r8-r11 showed legacy-HMMA
// issue ceiling (tensor pinned ~23% = legacy peak); fp8 halves lo-term
// instruction count -> -23.5% tensor instructions.
#define NIT 9
#define NSLOT 3
#define STAGE_BYTES 57344      // Ahi 16K | Alo 16K (fp16) / Slo8 8K | Bhi 16K | Blo8 8K
#define A_LO_OFF 16384
#define B_OFF    32768
#define B_LO_OFF 49152

__device__ __forceinline__ uint32_t sw_off(int row, int colByte) {
    // 128B rows, XOR-swizzled 16B chunks == TMA SW128 atom layout
    return (uint32_t)(row * 128 + ((((colByte >> 4) ^ (row & 7)) << 4) | (colByte & 15)));
}

__global__ __launch_bounds__(256) void step_kernel(
    const __grid_constant__ TMaps tm, int t) {
    extern __shared__ __align__(1024) char smem[];
    __shared__ __align__(8) uint64_t s_mbar[NSLOT];

    const int tid  = threadIdx.x;
    const int lane = tid & 31;
    const int warp = tid >> 5;
    const int warpM = warp & 3;     // 4 warps along M (16 rows each)
    const int warpN = warp >> 2;    // 2 warps along N (32 cols each)
    const int rowBase = blockIdx.y * 64;
    const int colBase = blockIdx.x * 64;
    const int pp = t & 1;

    const uint32_t smem_u32 = (uint32_t)__cvta_generic_to_shared(smem);
    const uint32_t mbar0    = (uint32_t)__cvta_generic_to_shared(s_mbar);

    const CUtensorMap* mShi  = &tm.shi[pp];
    const CUtensorMap* mSlo8 = &tm.slo8[pp];

    if (tid == 0) {
        #pragma unroll
        for (int s = 0; s < NSLOT; s++) MBARRIER_INIT(mbar0 + s * 8, 1);
    }
    __syncthreads();

    auto issue = [&](int kk) {
        uint32_t base = smem_u32 + (kk % NSLOT) * STAGE_BYTES;
        uint32_t mb   = mbar0 + (kk % NSLOT) * 8;
        if (kk < 8) {
            int k0 = kk << 7;
            MBARRIER_EXPECT_TX(mb, 49152u);
            tma2d(base,                mShi,  k0,      rowBase, mb);
            tma2d(base + 8192,         mShi,  k0 + 64, rowBase, mb);
            tma2d(base + A_LO_OFF,     mSlo8, k0,      rowBase, mb);   // 128B x 64 rows
            tma2d(base + B_OFF,        &tm.w, colBase, k0,      mb);
            tma2d(base + B_OFF + 8192, &tm.w, colBase, k0 + 64, mb);
            tma2d(base + B_LO_OFF,     &tm.w8T, k0,    colBase, mb);   // 128B x 64 n-rows
        } else {
            MBARRIER_EXPECT_TX(mb, 24576u);
            tma3d(base,            &tm.xhi, 0, t, rowBase, mb);
            tma3d(base + A_LO_OFF, &tm.xlo, 0, t, rowBase, mb);
            tma2d(base + B_OFF,    &tm.win, colBase, 0, mb);
        }
    };

    if (tid == 0) { issue(0); issue(1); }

    float acch[4][4];                // fp16-scale accumulator
    float accl[4][4];                // fp8 product accumulator (scale 2^16)
    #pragma unroll
    for (int j = 0; j < 4; j++)
        #pragma unroll
        for (int q = 0; q < 4; q++) { acch[j][q] = 0.0f; accl[j][q] = 0.0f; }

    for (int kk = 0; kk < NIT; kk++) {
        __syncthreads();
        if (tid == 0 && kk + 2 < NIT) issue(kk + 2);
        MBARRIER_WAIT_PARITY(mbar0 + (kk % NSLOT) * 8, (uint32_t)((kk / NSLOT) & 1));

        uint32_t base = smem_u32 + (kk % NSLOT) * STAGE_BYTES;

        if (kk < 8) {
            // ---- main stage: hi fp16 (8 x k16) + lo fp8 (4 x k32) ----
            #pragma unroll 8
            for (int kf = 0; kf < 8; kf++) {
                const uint32_t sub = (uint32_t)(kf >> 2) * 8192;
                const int kfl = kf & 3;
                uint32_t ahi[4];
                {
                    int row = warpM * 16 + (lane & 15);
                    int colByte = kfl * 32 + (lane >> 4) * 16;
                    asm volatile("ldmatrix.sync.aligned.m8n8.x4.shared.b16 {%0,%1,%2,%3}, [%4];"
                        : "=r"(ahi[0]), "=r"(ahi[1]), "=r"(ahi[2]), "=r"(ahi[3])
                        : "r"(base + sub + sw_off(row, colByte)));
                }
                uint32_t b[2][4];
                #pragma unroll
                for (int nh = 0; nh < 2; nh++) {
                    int krow = kfl * 16 + (lane & 7) + ((lane >> 3) & 1) * 8;
                    int colByte = (warpN * 32 + nh * 16 + (lane >> 4) * 8) * 2;
                    asm volatile("ldmatrix.sync.aligned.m8n8.x4.trans.shared.b16 {%0,%1,%2,%3}, [%4];"
                        : "=r"(b[nh][0]), "=r"(b[nh][1]), "=r"(b[nh][2]), "=r"(b[nh][3])
                        : "r"(base + B_OFF + sub + sw_off(krow, colByte)));
                }
                #pragma unroll
                for (int j = 0; j < 4; j++) {
                    uint32_t b0 = b[j >> 1][(j & 1) * 2], b1 = b[j >> 1][(j & 1) * 2 + 1];
                    asm volatile(
                        "mma.sync.aligned.m16n8k16.row.col.f32.f16.f16.f32 "
                        "{%0,%1,%2,%3}, {%4,%5,%6,%7}, {%8,%9}, {%0,%1,%2,%3};"
                        : "+f"(acch[j][0]), "+f"(acch[j][1]), "+f"(acch[j][2]), "+f"(acch[j][3])
                        : "r"(ahi[0]), "r"(ahi[1]), "r"(ahi[2]), "r"(ahi[3]), "r"(b0), "r"(b1));
                }
                if ((kf & 1) == 0) {
                    const int kf8 = kf >> 1;       // k32 slice 0..3
                    uint32_t a8[4];
                    {
                        int row = warpM * 16 + (lane & 15);
                        int colByte = kf8 * 32 + (lane >> 4) * 16;
                        asm volatile("ldmatrix.sync.aligned.m8n8.x4.shared.b16 {%0,%1,%2,%3}, [%4];"
                            : "=r"(a8[0]), "=r"(a8[1]), "=r"(a8[2]), "=r"(a8[3])
                            : "r"(base + A_LO_OFF + sw_off(row, colByte)));
                    }
                    uint32_t q0[4], q1[4];        // b0/b1 for 4 n8-groups
                    {
                        int n = warpN * 32 + lane;
                        asm volatile("ldmatrix.sync.aligned.m8n8.x4.shared.b16 {%0,%1,%2,%3}, [%4];"
                            : "=r"(q0[0]), "=r"(q0[1]), "=r"(q0[2]), "=r"(q0[3])
                            : "r"(base + B_LO_OFF + sw_off(n, kf8 * 32)));
                        asm volatile("ldmatrix.sync.aligned.m8n8.x4.shared.b16 {%0,%1,%2,%3}, [%4];"
                            : "=r"(q1[0]), "=r"(q1[1]), "=r"(q1[2]), "=r"(q1[3])
                            : "r"(base + B_LO_OFF + sw_off(n, kf8 * 32 + 16)));
                    }
                    #pragma unroll
                    for (int j = 0; j < 4; j++) {
                        asm volatile(
                            "mma.sync.aligned.m16n8k32.row.col.f32.e4m3.e4m3.f32 "
                            "{%0,%1,%2,%3}, {%4,%5,%6,%7}, {%8,%9}, {%0,%1,%2,%3};"
                            : "+f"(accl[j][0]), "+f"(accl[j][1]), "+f"(accl[j][2]), "+f"(accl[j][3])
                            : "r"(a8[0]), "r"(a8[1]), "r"(a8[2]), "r"(a8[3]),
                              "r"(q0[j]), "r"(q1[j]));
                    }
                }
            }
        } else {
            // ---- input stage: hi + lo both fp16 (4 x k16), into acch ----
            #pragma unroll 4
            for (int kf = 0; kf < 4; kf++) {
                uint32_t ahi[4], alo[4];
                {
                    int row = warpM * 16 + (lane & 15);
                    int colByte = kf * 32 + (lane >> 4) * 16;
                    uint32_t so = sw_off(row, colByte);
                    asm volatile("ldmatrix.sync.aligned.m8n8.x4.shared.b16 {%0,%1,%2,%3}, [%4];"
                        : "=r"(ahi[0]), "=r"(ahi[1]), "=r"(ahi[2]), "=r"(ahi[3])
                        : "r"(base + so));
                    asm volatile("ldmatrix.sync.aligned.m8n8.x4.shared.b16 {%0,%1,%2,%3}, [%4];"
                        : "=r"(alo[0]), "=r"(alo[1]), "=r"(alo[2]), "=r"(alo[3])
                        : "r"(base + A_LO_OFF + so));
                }
                uint32_t b[2][4];
                #pragma unroll
                for (int nh = 0; nh < 2; nh++) {
                    int krow = kf * 16 + (lane & 7) + ((lane >> 3) & 1) * 8;
                    int colByte = (warpN * 32 + nh * 16 + (lane >> 4) * 8) * 2;
                    asm volatile("ldmatrix.sync.aligned.m8n8.x4.trans.shared.b16 {%0,%1,%2,%3}, [%4];"
                        : "=r"(b[nh][0]), "=r"(b[nh][1]), "=r"(b[nh][2]), "=r"(b[nh][3])
                        : "r"(base + B_OFF + sw_off(krow, colByte)));
                }
                #pragma unroll
                for (int j = 0; j < 4; j++) {
                    uint32_t b0 = b[j >> 1][(j & 1) * 2], b1 = b[j >> 1][(j & 1) * 2 + 1];
                    asm volatile(
                        "mma.sync.aligned.m16n8k16.row.col.f32.f16.f16.f32 "
                        "{%0,%1,%2,%3}, {%4,%5,%6,%7}, {%8,%9}, {%0,%1,%2,%3};"
                        : "+f"(acch[j][0]), "+f"(acch[j][1]), "+f"(acch[j][2]), "+f"(acch[j][3])
                        : "r"(ahi[0]), "r"(ahi[1]), "r"(ahi[2]), "r"(ahi[3]), "r"(b0), "r"(b1));
                    asm volatile(
                        "mma.sync.aligned.m16n8k16.row.col.f32.f16.f16.f32 "
                        "{%0,%1,%2,%3}, {%4,%5,%6,%7}, {%8,%9}, {%0,%1,%2,%3};"
                        : "+f"(acch[j][0]), "+f"(acch[j][1]), "+f"(acch[j][2]), "+f"(acch[j][3])
                        : "r"(alo[0]), "r"(alo[1]), "r"(alo[2]), "r"(alo[3]), "r"(b0), "r"(b1));
                }
            }
        }
    }

    // ---- epilogue: combine, leaky tanh, in-place fp32 state, emit hi/lo8 ----
    __half* __restrict__ shiN = g_shi[pp ^ 1];
    unsigned char* __restrict__ slo8N = g_slo8[pp ^ 1];
    const float LSCALE = 1.0f / 65536.0f;   // 2^-12 (Slo) * 2^-4 (W)
    #pragma unroll
    for (int j = 0; j < 4; j++)
        #pragma unroll
        for (int h = 0; h < 2; h++) {
            int row = rowBase + warpM * 16 + (lane >> 2) + 8 * h;
            int col = colBase + warpN * 32 + j * 8 + (lane & 3) * 2;
            long long idx = (long long)row * RES + col;
            float y0 = fmaf(accl[j][h * 2 + 0], LSCALE, acch[j][h * 2 + 0]);
            float y1 = fmaf(accl[j][h * 2 + 1], LSCALE, acch[j][h * 2 + 1]);
            float2 sold = *reinterpret_cast<float2*>(&g_state[idx]);
            float n0 = 0.5f * sold.x + 0.5f * fast_tanhf(y0);
            float n1 = 0.5f * sold.y + 0.5f * fast_tanhf(y1);
            *reinterpret_cast<float2*>(&g_state[idx]) = make_float2(n0, n1);
            __half h0 = __float2half(n0);
            __half h1 = __float2half(n1);
            __half2 hv; hv.x = h0; hv.y = h1;
            *reinterpret_cast<__half2*>(&shiN[idx]) = hv;
            float l0 = (n0 - __half2float(h0)) * 4096.0f;
            float l1 = (n1 - __half2float(h1)) * 4096.0f;
            __nv_fp8x2_storage_t p =
                __nv_cvt_float2_to_fp8x2(make_float2(l0, l1), __NV_SATFINITE, __NV_E4M3);
            *reinterpret_cast<unsigned short*>(&slo8N[idx]) = (unsigned short)p;
        }
}

// ---------------- output GEMM ----------------------------------------------
__global__ __launch_bounds__(64) void output_kernel(
    const float* __restrict__ Wout, float* __restrict__ out) {
    __shared__ float srow[RES];
    const int b = blockIdx.x;
    const int j = threadIdx.x;
    for (int k = j; k < RES; k += 64) srow[k] = g_state[b * RES + k];
    __syncthreads();
    float sum = 0.0f;
    #pragma unroll 8
    for (int k = 0; k < RES; k++)
        sum = fmaf(srow[k], Wout[k * OUTSZ + j], sum);
    out[b * OUTSZ + j] = sum;
}

// ---------------- host: tensormap construction ------------------------------
typedef CUresult (*EncodeFn)(CUtensorMap*, CUtensorMapDataType, cuuint32_t, void*,
                             const cuuint64_t*, const cuuint64_t*, const cuuint32_t*,
                             const cuuint32_t*, CUtensorMapInterleave, CUtensorMapSwizzle,
                             CUtensorMapL2promotion, CUtensorMapFloatOOBfill);

static EncodeFn get_encode_fn() {
    void* p = nullptr;
#if CUDART_VERSION >= 12050
    cudaDriverEntryPointQueryResult st;
    cudaGetDriverEntryPointByVersion("cuTensorMapEncodeTiled", &p, 12000,
                                     cudaEnableDefault, &st);
#else
    cudaDriverEntryPointQueryResult st;
    cudaGetDriverEntryPoint("cuTensorMapEncodeTiled", &p, cudaEnableDefault, &st);
#endif
    return (EncodeFn)p;
}

static void enc2d(EncodeFn f, CUtensorMap* m, void* ptr,
                  uint64_t d0, uint64_t d1, uint64_t stride1B) {
    cuuint64_t dims[2] = {d0, d1};
    cuuint64_t strides[1] = {stride1B};
    cuuint32_t box[2] = {64, 64};
    cuuint32_t es[2] = {1, 1};
    f(m, CU_TENSOR_MAP_DATA_TYPE_FLOAT16, 2, ptr, dims, strides, box, es,
      CU_TENSOR_MAP_INTERLEAVE_NONE, CU_TENSOR_MAP_SWIZZLE_128B,
      CU_TENSOR_MAP_L2_PROMOTION_L2_128B, CU_TENSOR_MAP_FLOAT_OOB_FILL_NONE);
}

static void enc2d_u8(EncodeFn f, CUtensorMap* m, void* ptr,
                     uint64_t d0, uint64_t d1, uint64_t stride1B) {
    cuuint64_t dims[2] = {d0, d1};
    cuuint64_t strides[1] = {stride1B};
    cuuint32_t box[2] = {128, 64};       // 128B inner = SW128 atom
    cuuint32_t es[2] = {1, 1};
    f(m, CU_TENSOR_MAP_DATA_TYPE_UINT8, 2, ptr, dims, strides, box, es,
      CU_TENSOR_MAP_INTERLEAVE_NONE, CU_TENSOR_MAP_SWIZZLE_128B,
      CU_TENSOR_MAP_L2_PROMOTION_L2_128B, CU_TENSOR_MAP_FLOAT_OOB_FILL_NONE);
}

static void enc3d_x(EncodeFn f, CUtensorMap* m, void* ptr) {
    cuuint64_t dims[3] = {INSZ, SEQLEN, BATCH};
    cuuint64_t strides[2] = {INSZ * 2ull, (uint64_t)SEQLEN * INSZ * 2ull};
    cuuint32_t box[3] = {64, 1, 64};
    cuuint32_t es[3] = {1, 1, 1};
    f(m, CU_TENSOR_MAP_DATA_TYPE_FLOAT16, 3, ptr, dims, strides, box, es,
      CU_TENSOR_MAP_INTERLEAVE_NONE, CU_TENSOR_MAP_SWIZZLE_128B,
      CU_TENSOR_MAP_L2_PROMOTION_L2_128B, CU_TENSOR_MAP_FLOAT_OOB_FILL_NONE);
}

// ---------------- launch ----------------------------------------------------
extern "C" void kernel_launch(void* const* d_in, const int* in_sizes, int n_in,
                              void* d_out, int out_size) {
    const float* input = (const float*)d_in[0];   // [512,512,64]
    const float* Wres  = (const float*)d_in[1];   // [1024,1024]
    const float* Win   = (const float*)d_in[2];   // [64,1024]
    const float* Wout  = (const float*)d_in[3];   // [1024,64]
    float* out = (float*)d_out;

    void *shi, *slo8, *w16, *w8T, *win16, *xhi, *xlo;
    cudaGetSymbolAddress(&shi,   g_shi);
    cudaGetSymbolAddress(&slo8,  g_slo8);
    cudaGetSymbolAddress(&w16,   g_w16);
    cudaGetSymbolAddress(&w8T,   g_w8T);
    cudaGetSymbolAddress(&win16, g_win16);
    cudaGetSymbolAddress(&xhi,   g_xhi);
    cudaGetSymbolAddress(&xlo,   g_xlo);

    EncodeFn enc = get_encode_fn();
    TMaps tm;
    enc2d(enc, &tm.shi[0], shi, RES, BATCH, RES * 2ull);
    enc2d(enc, &tm.shi[1], (char*)shi + (size_t)BATCH * RES * 2, RES, BATCH, RES * 2ull);
    enc2d_u8(enc, &tm.slo8[0], slo8, RES, BATCH, RES);
    enc2d_u8(enc, &tm.slo8[1], (char*)slo8 + (size_t)BATCH * RES, RES, BATCH, RES);
    enc2d(enc, &tm.w, w16, RES, RES, RES * 2ull);
    enc2d_u8(enc, &tm.w8T, w8T, RES, RES, RES);
    enc2d(enc, &tm.win, win16, RES, INSZ, RES * 2ull);
    enc3d_x(enc, &tm.xhi, xhi);
    enc3d_x(enc, &tm.xlo, xlo);

    cudaFuncSetAttribute(step_kernel,
                         cudaFuncAttributeMaxDynamicSharedMemorySize,
                         NSLOT * STAGE_BYTES);

    prep_kernel<<<4096, 256>>>(input, Wres, Win);
    w8t_kernel<<<dim3(32, 32), dim3(32, 8)>>>(Wres);

    dim3 grid(RES / 64, BATCH / 64);   // (16, 8) = 128 CTAs
    for (int t = 0; t < SEQLEN; t++)
        step_kernel<<<grid, 256, NSLOT * STAGE_BYTES>>>(tm, t);

    output_kernel<<<BATCH, 64>>>(Wout, out);
}

// round 13
// speedup vs baseline: 1.1877x; 1.1877x over previous
#include <cuda_runtime.h>
#include <cuda.h>
#include <cuda_fp16.h>
#include <cstdint>

#define BATCH 512
#define SEQLEN 512
#define INSZ 64
#define RES 1024
#define OUTSZ 64

// ---------------- static device buffers (no allocation allowed) -------------
__device__ float g_state[BATCH * RES];              // fp32 state, in-place
__device__ __half g_shi[2][BATCH * RES];            // state hi (fp16), ping-pong
__device__ __half g_slo[2][BATCH * RES];            // state lo (fp16), ping-pong
__device__ __half g_w16[RES * RES];                 // W_res in fp16
__device__ __half g_win16[INSZ * RES];              // W_in in fp16
__device__ __half g_xhi[BATCH * SEQLEN * INSZ];     // input hi
__device__ __half g_xlo[BATCH * SEQLEN * INSZ];     // input lo

struct TMaps {
    CUtensorMap shi[2];
    CUtensorMap slo[2];
    CUtensorMap w;
    CUtensorMap win;
    CUtensorMap xhi;
    CUtensorMap xlo;
};

// ---------------- merged prep kernel (ONE launch) ---------------------------
__global__ void prep_kernel(const float* __restrict__ input,
                            const float* __restrict__ Wres,
                            const float* __restrict__ Win) {
    int i = blockIdx.x * blockDim.x + threadIdx.x;
    int stride = gridDim.x * blockDim.x;
    const __half z = __float2half(0.0f);
    for (int k = i; k < BATCH * SEQLEN * INSZ; k += stride) {
        float v = input[k];
        __half h = __float2half(v);
        g_xhi[k] = h;
        g_xlo[k] = __float2half(v - __half2float(h));
        if (k < RES * RES) g_w16[k] = __float2half(Wres[k]);
        if (k < INSZ * RES) g_win16[k] = __float2half(Win[k]);
        if (k < BATCH * RES) {
            g_state[k] = 0.0f;
            g_shi[0][k] = z;
            g_slo[0][k] = z;
        }
    }
}

// ---------------- fast tanh (ex2 + rcp approx; abs err ~1e-6) ---------------
__device__ __forceinline__ float fast_tanhf(float x) {
    float e;
    asm("ex2.approx.f32 %0, %1;" : "=f"(e) : "f"(x * 2.8853900817779268f));
    float r;
    asm("rcp.approx.f32 %0, %1;" : "=f"(r) : "f"(e + 1.0f));
    return fmaf(-2.0f, r, 1.0f);
}

// ---------------- PTX helpers ------------------------------------------------
#define MBARRIER_INIT(addr, cnt) \
    asm volatile("mbarrier.init.shared.b64 [%0], %1;" :: "r"(addr), "r"(cnt) : "memory")

#define MBARRIER_EXPECT_TX(addr, bytes) \
    asm volatile("mbarrier.arrive.expect_tx.shared.b64 _, [%0], %1;" \
                 :: "r"(addr), "r"(bytes) : "memory")

#define MBARRIER_WAIT_PARITY(mbar, par) do {                                   \
    uint32_t _m = (mbar); uint32_t _p = (par); uint32_t _done;                 \
    asm volatile("{\n\t.reg .pred p;\n\t"                                      \
        "mbarrier.try_wait.parity.acquire.cta.shared::cta.b64 p, [%1], %2;\n\t"\
        "selp.b32 %0, 1, 0, p;\n\t}" : "=r"(_done) : "r"(_m), "r"(_p) : "memory"); \
    if (!_done) {                                                              \
        asm volatile("{\n\t.reg .pred P1;\n\tWL_%=:\n\t"                       \
            "mbarrier.try_wait.parity.acquire.cta.shared::cta.b64 P1, [%0], %1, 0x989680;\n\t" \
            "@P1 bra.uni WD_%=;\n\tbra.uni WL_%=;\n\tWD_%=:\n\t}"              \
            :: "r"(_m), "r"(_p) : "memory");                                   \
    }                                                                          \
} while (0)

__device__ __forceinline__ void tma2d(uint32_t dst, const CUtensorMap* m,
                                      int c0, int c1, uint32_t mbar) {
    asm volatile(
        "cp.async.bulk.tensor.2d.shared::cluster.global.tile.mbarrier::complete_tx::bytes "
        "[%0], [%1, {%2, %3}], [%4];"
        :: "r"(dst), "l"(m), "r"(c0), "r"(c1), "r"(mbar) : "memory");
}

__device__ __forceinline__ void tma3d(uint32_t dst, const CUtensorMap* m,
                                      int c0, int c1, int c2, uint32_t mbar) {
    asm volatile(
        "cp.async.bulk.tensor.3d.shared::cluster.global.tile.mbarrier::complete_tx::bytes "
        "[%0], [%1, {%2, %3, %4}], [%5];"
        :: "r"(dst), "l"(m), "r"(c0), "r"(c1), "r"(c2), "r"(mbar) : "memory");
}

// ---------------- step kernel ----------------------------------------------
// Y = Shi@W16 + Slo@W16 + xhi@Win16 + xlo@Win16 (2-product fp16 split).
// 9 K-blocks (8 x BK128 + 1 x BK64 input). TMA loader (6/stage), 3-slot ring,
// 256 threads (8 warps, 4Mx2N, warp tile 16x32).
// r13 changes vs r10: (a) explicit fragment double-buffering - kf+1 LDSMs
// issue before kf MMAs (hide LDS latency); (b) split acch/accl chains ->
// 8 independent MMA chains per warp (hide HMMA latency).
#define NIT 9
#define NSLOT 3
#define STAGE_BYTES 49152      // Ahi 16K | Alo 16K | B 16K
#define A_LO_OFF 16384
#define B_OFF    32768

__device__ __forceinline__ uint32_t sw_off(int row, int colByte) {
    // 128B rows, XOR-swizzled 16B chunks == TMA SW128 atom layout
    return (uint32_t)(row * 128 + ((((colByte >> 4) ^ (row & 7)) << 4) | (colByte & 15)));
}

template<int NKF>
__device__ __forceinline__ void do_block(uint32_t base, int lane, int warpM, int warpN,
                                         float (&acch)[4][4], float (&accl)[4][4]) {
    uint32_t fa[2][2][4];   // [buf][hi/lo][regs]
    uint32_t fb[2][2][4];   // [buf][nh][regs]

    auto ld = [&](int kf, int buf) {
        const uint32_t sub = (uint32_t)(kf >> 2) * 8192;
        const int kfl = kf & 3;
        {
            int row = warpM * 16 + (lane & 15);
            int colByte = kfl * 32 + (lane >> 4) * 16;
            uint32_t so = sw_off(row, colByte);
            asm volatile("ldmatrix.sync.aligned.m8n8.x4.shared.b16 {%0,%1,%2,%3}, [%4];"
                : "=r"(fa[buf][0][0]), "=r"(fa[buf][0][1]),
                  "=r"(fa[buf][0][2]), "=r"(fa[buf][0][3])
                : "r"(base + sub + so));
            asm volatile("ldmatrix.sync.aligned.m8n8.x4.shared.b16 {%0,%1,%2,%3}, [%4];"
                : "=r"(fa[buf][1][0]), "=r"(fa[buf][1][1]),
                  "=r"(fa[buf][1][2]), "=r"(fa[buf][1][3])
                : "r"(base + A_LO_OFF + sub + so));
        }
        #pragma unroll
        for (int nh = 0; nh < 2; nh++) {
            int krow = kfl * 16 + (lane & 7) + ((lane >> 3) & 1) * 8;
            int colByte = (warpN * 32 + nh * 16 + (lane >> 4) * 8) * 2;
            asm volatile("ldmatrix.sync.aligned.m8n8.x4.trans.shared.b16 {%0,%1,%2,%3}, [%4];"
                : "=r"(fb[buf][nh][0]), "=r"(fb[buf][nh][1]),
                  "=r"(fb[buf][nh][2]), "=r"(fb[buf][nh][3])
                : "r"(base + B_OFF + sub + sw_off(krow, colByte)));
        }
    };

    ld(0, 0);
    #pragma unroll
    for (int kf = 0; kf < NKF; kf++) {
        const int cur = kf & 1;
        if (kf + 1 < NKF) ld(kf + 1, cur ^ 1);     // prefetch next slice's frags
        #pragma unroll
        for (int j = 0; j < 4; j++) {
            uint32_t b0 = fb[cur][j >> 1][(j & 1) * 2];
            uint32_t b1 = fb[cur][j >> 1][(j & 1) * 2 + 1];
            asm volatile(
                "mma.sync.aligned.m16n8k16.row.col.f32.f16.f16.f32 "
                "{%0,%1,%2,%3}, {%4,%5,%6,%7}, {%8,%9}, {%0,%1,%2,%3};"
                : "+f"(acch[j][0]), "+f"(acch[j][1]), "+f"(acch[j][2]), "+f"(acch[j][3])
                : "r"(fa[cur][0][0]), "r"(fa[cur][0][1]),
                  "r"(fa[cur][0][2]), "r"(fa[cur][0][3]), "r"(b0), "r"(b1));
            asm volatile(
                "mma.sync.aligned.m16n8k16.row.col.f32.f16.f16.f32 "
                "{%0,%1,%2,%3}, {%4,%5,%6,%7}, {%8,%9}, {%0,%1,%2,%3};"
                : "+f"(accl[j][0]), "+f"(accl[j][1]), "+f"(accl[j][2]), "+f"(accl[j][3])
                : "r"(fa[cur][1][0]), "r"(fa[cur][1][1]),
                  "r"(fa[cur][1][2]), "r"(fa[cur][1][3]), "r"(b0), "r"(b1));
        }
    }
}

__global__ __launch_bounds__(256) void step_kernel(
    const __grid_constant__ TMaps tm, int t) {
    extern __shared__ __align__(1024) char smem[];
    __shared__ __align__(8) uint64_t s_mbar[NSLOT];

    const int tid  = threadIdx.x;
    const int lane = tid & 31;
    const int warp = tid >> 5;
    const int warpM = warp & 3;     // 4 warps along M (16 rows each)
    const int warpN = warp >> 2;    // 2 warps along N (32 cols each)
    const int rowBase = blockIdx.y * 64;
    const int colBase = blockIdx.x * 64;
    const int pp = t & 1;

    const uint32_t smem_u32 = (uint32_t)__cvta_generic_to_shared(smem);
    const uint32_t mbar0    = (uint32_t)__cvta_generic_to_shared(s_mbar);

    const CUtensorMap* mShi = &tm.shi[pp];
    const CUtensorMap* mSlo = &tm.slo[pp];

    if (tid == 0) {
        #pragma unroll
        for (int s = 0; s < NSLOT; s++) MBARRIER_INIT(mbar0 + s * 8, 1);
    }
    __syncthreads();

    auto issue = [&](int kk) {
        uint32_t base = smem_u32 + (kk % NSLOT) * STAGE_BYTES;
        uint32_t mb   = mbar0 + (kk % NSLOT) * 8;
        if (kk < 8) {
            int k0 = kk << 7;
            MBARRIER_EXPECT_TX(mb, 49152u);
            tma2d(base,                   mShi, k0,      rowBase, mb);
            tma2d(base + 8192,            mShi, k0 + 64, rowBase, mb);
            tma2d(base + A_LO_OFF,        mSlo, k0,      rowBase, mb);
            tma2d(base + A_LO_OFF + 8192, mSlo, k0 + 64, rowBase, mb);
            tma2d(base + B_OFF,           &tm.w, colBase, k0,      mb);
            tma2d(base + B_OFF + 8192,    &tm.w, colBase, k0 + 64, mb);
        } else {
            MBARRIER_EXPECT_TX(mb, 24576u);
            tma3d(base,            &tm.xhi, 0, t, rowBase, mb);
            tma3d(base + A_LO_OFF, &tm.xlo, 0, t, rowBase, mb);
            tma2d(base + B_OFF,    &tm.win, colBase, 0, mb);
        }
    };

    if (tid == 0) { issue(0); issue(1); }

    float acch[4][4], accl[4][4];
    #pragma unroll
    for (int j = 0; j < 4; j++)
        #pragma unroll
        for (int q = 0; q < 4; q++) { acch[j][q] = 0.0f; accl[j][q] = 0.0f; }

    for (int kk = 0; kk < NIT; kk++) {
        __syncthreads();             // all warps done reading slot (kk+2)%NSLOT
        if (tid == 0 && kk + 2 < NIT) issue(kk + 2);
        MBARRIER_WAIT_PARITY(mbar0 + (kk % NSLOT) * 8, (uint32_t)((kk / NSLOT) & 1));

        uint32_t base = smem_u32 + (kk % NSLOT) * STAGE_BYTES;
        if (kk < 8) do_block<8>(base, lane, warpM, warpN, acch, accl);
        else        do_block<4>(base, lane, warpM, warpN, acch, accl);
    }

    // ---- epilogue: combine hi/lo, leaky tanh; in-place fp32 state,
    //      emit fp16 hi/lo for next step ----
    __half* __restrict__ shiN = g_shi[pp ^ 1];
    __half* __restrict__ sloN = g_slo[pp ^ 1];
    #pragma unroll
    for (int j = 0; j < 4; j++)
        #pragma unroll
        for (int h = 0; h < 2; h++) {
            int row = rowBase + warpM * 16 + (lane >> 2) + 8 * h;
            int col = colBase + warpN * 32 + j * 8 + (lane & 3) * 2;
            long long idx = (long long)row * RES + col;
            float y0 = acch[j][h * 2 + 0] + accl[j][h * 2 + 0];
            float y1 = acch[j][h * 2 + 1] + accl[j][h * 2 + 1];
            float2 sold = *reinterpret_cast<float2*>(&g_state[idx]);
            float n0 = 0.5f * sold.x + 0.5f * fast_tanhf(y0);
            float n1 = 0.5f * sold.y + 0.5f * fast_tanhf(y1);
            *reinterpret_cast<float2*>(&g_state[idx]) = make_float2(n0, n1);
            __half h0 = __float2half(n0);
            __half h1 = __float2half(n1);
            __half2 hv; hv.x = h0; hv.y = h1;
            __half2 lv;
            lv.x = __float2half(n0 - __half2float(h0));
            lv.y = __float2half(n1 - __half2float(h1));
            *reinterpret_cast<__half2*>(&shiN[idx]) = hv;
            *reinterpret_cast<__half2*>(&sloN[idx]) = lv;
        }
}

// ---------------- output GEMM ----------------------------------------------
__global__ __launch_bounds__(64) void output_kernel(
    const float* __restrict__ Wout, float* __restrict__ out) {
    __shared__ float srow[RES];
    const int b = blockIdx.x;
    const int j = threadIdx.x;
    for (int k = j; k < RES; k += 64) srow[k] = g_state[b * RES + k];
    __syncthreads();
    float sum = 0.0f;
    #pragma unroll 8
    for (int k = 0; k < RES; k++)
        sum = fmaf(srow[k], Wout[k * OUTSZ + j], sum);
    out[b * OUTSZ + j] = sum;
}

// ---------------- host: tensormap construction ------------------------------
typedef CUresult (*EncodeFn)(CUtensorMap*, CUtensorMapDataType, cuuint32_t, void*,
                             const cuuint64_t*, const cuuint64_t*, const cuuint32_t*,
                             const cuuint32_t*, CUtensorMapInterleave, CUtensorMapSwizzle,
                             CUtensorMapL2promotion, CUtensorMapFloatOOBfill);

static EncodeFn get_encode_fn() {
    void* p = nullptr;
#if CUDART_VERSION >= 12050
    cudaDriverEntryPointQueryResult st;
    cudaGetDriverEntryPointByVersion("cuTensorMapEncodeTiled", &p, 12000,
                                     cudaEnableDefault, &st);
#else
    cudaDriverEntryPointQueryResult st;
    cudaGetDriverEntryPoint("cuTensorMapEncodeTiled", &p, cudaEnableDefault, &st);
#endif
    return (EncodeFn)p;
}

static void enc2d(EncodeFn f, CUtensorMap* m, void* ptr,
                  uint64_t d0, uint64_t d1, uint64_t stride1B) {
    cuuint64_t dims[2] = {d0, d1};
    cuuint64_t strides[1] = {stride1B};
    cuuint32_t box[2] = {64, 64};
    cuuint32_t es[2] = {1, 1};
    f(m, CU_TENSOR_MAP_DATA_TYPE_FLOAT16, 2, ptr, dims, strides, box, es,
      CU_TENSOR_MAP_INTERLEAVE_NONE, CU_TENSOR_MAP_SWIZZLE_128B,
      CU_TENSOR_MAP_L2_PROMOTION_L2_128B, CU_TENSOR_MAP_FLOAT_OOB_FILL_NONE);
}

static void enc3d_x(EncodeFn f, CUtensorMap* m, void* ptr) {
    cuuint64_t dims[3] = {INSZ, SEQLEN, BATCH};
    cuuint64_t strides[2] = {INSZ * 2ull, (uint64_t)SEQLEN * INSZ * 2ull};
    cuuint32_t box[3] = {64, 1, 64};
    cuuint32_t es[3] = {1, 1, 1};
    f(m, CU_TENSOR_MAP_DATA_TYPE_FLOAT16, 3, ptr, dims, strides, box, es,
      CU_TENSOR_MAP_INTERLEAVE_NONE, CU_TENSOR_MAP_SWIZZLE_128B,
      CU_TENSOR_MAP_L2_PROMOTION_L2_128B, CU_TENSOR_MAP_FLOAT_OOB_FILL_NONE);
}

// ---------------- launch ----------------------------------------------------
extern "C" void kernel_launch(void* const* d_in, const int* in_sizes, int n_in,
                              void* d_out, int out_size) {
    const float* input = (const float*)d_in[0];   // [512,512,64]
    const float* Wres  = (const float*)d_in[1];   // [1024,1024]
    const float* Win   = (const float*)d_in[2];   // [64,1024]
    const float* Wout  = (const float*)d_in[3];   // [1024,64]
    float* out = (float*)d_out;

    void *shi, *slo, *w16, *win16, *xhi, *xlo;
    cudaGetSymbolAddress(&shi,   g_shi);
    cudaGetSymbolAddress(&slo,   g_slo);
    cudaGetSymbolAddress(&w16,   g_w16);
    cudaGetSymbolAddress(&win16, g_win16);
    cudaGetSymbolAddress(&xhi,   g_xhi);
    cudaGetSymbolAddress(&xlo,   g_xlo);

    EncodeFn enc = get_encode_fn();
    TMaps tm;
    enc2d(enc, &tm.shi[0], shi, RES, BATCH, RES * 2ull);
    enc2d(enc, &tm.shi[1], (char*)shi + (size_t)BATCH * RES * 2, RES, BATCH, RES * 2ull);
    enc2d(enc, &tm.slo[0], slo, RES, BATCH, RES * 2ull);
    enc2d(enc, &tm.slo[1], (char*)slo + (size_t)BATCH * RES * 2, RES, BATCH, RES * 2ull);
    enc2d(enc, &tm.w, w16, RES, RES, RES * 2ull);
    enc2d(enc, &tm.win, win16, RES, INSZ, RES * 2ull);
    enc3d_x(enc, &tm.xhi, xhi);
    enc3d_x(enc, &tm.xlo, xlo);

    cudaFuncSetAttribute(step_kernel,
                         cudaFuncAttributeMaxDynamicSharedMemorySize,
                         NSLOT * STAGE_BYTES);

    prep_kernel<<<4096, 256>>>(input, Wres, Win);

    dim3 grid(RES / 64, BATCH / 64);   // (16, 8) = 128 CTAs
    for (int t = 0; t < SEQLEN; t++)
        step_kernel<<<grid, 256, NSLOT * STAGE_BYTES>>>(tm, t);

    output_kernel<<<BATCH, 64>>>(Wout, out);
}

// round 14
// speedup vs baseline: 1.2738x; 1.0724x over previous
#include <cuda_runtime.h>
#include <cuda.h>
#include <cuda_fp16.h>
#include <cstdint>

#define BATCH 512
#define SEQLEN 512
#define INSZ 64
#define RES 1024
#define OUTSZ 64

// ---------------- static device buffers (no allocation allowed) -------------
__device__ float g_state[BATCH * RES];              // fp32 state, in-place
__device__ __half g_shi[2][BATCH * RES];            // state hi (fp16), ping-pong
__device__ __half g_slo[2][BATCH * RES];            // state lo (fp16), ping-pong
__device__ __half g_w16[RES * RES];                 // W_res in fp16
__device__ __half g_win16[INSZ * RES];              // W_in in fp16
__device__ __half g_xhi[BATCH * SEQLEN * INSZ];     // input hi
__device__ __half g_xlo[BATCH * SEQLEN * INSZ];     // input lo

struct TMaps {
    CUtensorMap shi[2];   // fp16, box {64,32}
    CUtensorMap slo[2];   // fp16, box {64,32}
    CUtensorMap w;        // fp16, box {64,64}
    CUtensorMap win;      // fp16, box {64,64}
    CUtensorMap xhi;      // fp16 3D, box {64,1,32}
    CUtensorMap xlo;
    CUtensorMap st;       // fp32, box {64,32}, no swizzle
};

// ---------------- merged prep kernel (ONE launch) ---------------------------
__global__ void prep_kernel(const float* __restrict__ input,
                            const float* __restrict__ Wres,
                            const float* __restrict__ Win) {
    int i = blockIdx.x * blockDim.x + threadIdx.x;
    int stride = gridDim.x * blockDim.x;
    const __half z = __float2half(0.0f);
    for (int k = i; k < BATCH * SEQLEN * INSZ; k += stride) {
        float v = input[k];
        __half h = __float2half(v);
        g_xhi[k] = h;
        g_xlo[k] = __float2half(v - __half2float(h));
        if (k < RES * RES) g_w16[k] = __float2half(Wres[k]);
        if (k < INSZ * RES) g_win16[k] = __float2half(Win[k]);
        if (k < BATCH * RES) {
            g_state[k] = 0.0f;
            g_shi[0][k] = z;
            g_slo[0][k] = z;
        }
    }
}

// ---------------- fast tanh (ex2 + rcp approx; abs err ~1e-6) ---------------
__device__ __forceinline__ float fast_tanhf(float x) {
    float e;
    asm("ex2.approx.f32 %0, %1;" : "=f"(e) : "f"(x * 2.8853900817779268f));
    float r;
    asm("rcp.approx.f32 %0, %1;" : "=f"(r) : "f"(e + 1.0f));
    return fmaf(-2.0f, r, 1.0f);
}

// ---------------- PTX helpers ------------------------------------------------
#define MBARRIER_INIT(addr, cnt) \
    asm volatile("mbarrier.init.shared.b64 [%0], %1;" :: "r"(addr), "r"(cnt) : "memory")

#define MBARRIER_EXPECT_TX(addr, bytes) \
    asm volatile("mbarrier.arrive.expect_tx.shared.b64 _, [%0], %1;" \
                 :: "r"(addr), "r"(bytes) : "memory")

#define MBARRIER_WAIT_PARITY(mbar, par) do {                                   \
    uint32_t _m = (mbar); uint32_t _p = (par); uint32_t _done;                 \
    asm volatile("{\n\t.reg .pred p;\n\t"                                      \
        "mbarrier.try_wait.parity.acquire.cta.shared::cta.b64 p, [%1], %2;\n\t"\
        "selp.b32 %0, 1, 0, p;\n\t}" : "=r"(_done) : "r"(_m), "r"(_p) : "memory"); \
    if (!_done) {                                                              \
        asm volatile("{\n\t.reg .pred P1;\n\tWL_%=:\n\t"                       \
            "mbarrier.try_wait.parity.acquire.cta.shared::cta.b64 P1, [%0], %1, 0x989680;\n\t" \
            "@P1 bra.uni WD_%=;\n\tbra.uni WL_%=;\n\tWD_%=:\n\t}"              \
            :: "r"(_m), "r"(_p) : "memory");                                   \
    }                                                                          \
} while (0)

__device__ __forceinline__ void tma2d(uint32_t dst, const CUtensorMap* m,
                                      int c0, int c1, uint32_t mbar) {
    asm volatile(
        "cp.async.bulk.tensor.2d.shared::cluster.global.tile.mbarrier::complete_tx::bytes "
        "[%0], [%1, {%2, %3}], [%4];"
        :: "r"(dst), "l"(m), "r"(c0), "r"(c1), "r"(mbar) : "memory");
}

__device__ __forceinline__ void tma3d(uint32_t dst, const CUtensorMap* m,
                                      int c0, int c1, int c2, uint32_t mbar) {
    asm volatile(
        "cp.async.bulk.tensor.3d.shared::cluster.global.tile.mbarrier::complete_tx::bytes "
        "[%0], [%1, {%2, %3, %4}], [%5];"
        :: "r"(dst), "l"(m), "r"(c0), "r"(c1), "r"(c2), "r"(mbar) : "memory");
}

// ---------------- step kernel ----------------------------------------------
// Y = Shi@W16 + Slo@W16 + xhi@Win16 + xlo@Win16 (2-product fp16 split).
// r14: tile BM=32 x BN=64, grid (16,16)=256 CTAs, 128 threads (4 warps 2Mx2N,
// warp tile 16x32 = r13 pattern). 2 CTAs/SM -> independent barrier domains +
// TMA streams overlap each other's syncs/epilogues. fp32 state tile is TMA-
// prefetched into smem at kernel start (overlapped with GEMM) so the epilogue
// RMW reads smem, not L2.
#define NIT 9
#define NSLOT 3
#define STAGE_BYTES 32768      // Ahi 8K | Alo 8K | B 16K
#define A_LO_OFF 8192
#define B_OFF    16384
#define ST_OFF   (NSLOT * STAGE_BYTES)          // fp32 state tile 32x64 = 8K
#define SMEM_TOTAL (ST_OFF + 8192)

__device__ __forceinline__ uint32_t sw_off(int row, int colByte) {
    // 128B rows, XOR-swizzled 16B chunks == TMA SW128 atom layout
    return (uint32_t)(row * 128 + ((((colByte >> 4) ^ (row & 7)) << 4) | (colByte & 15)));
}

template<int NKF>
__device__ __forceinline__ void do_block(uint32_t base, int lane, int warpM, int warpN,
                                         float (&acch)[4][4], float (&accl)[4][4]) {
    uint32_t fa[2][2][4];   // [buf][hi/lo][regs]
    uint32_t fb[2][2][4];   // [buf][nh][regs]

    auto ld = [&](int kf, int buf) {
        const int kfl = kf & 3;
        {
            const uint32_t sub = (uint32_t)(kf >> 2) * 4096;   // A half-tiles 4K
            int row = warpM * 16 + (lane & 15);
            int colByte = kfl * 32 + (lane >> 4) * 16;
            uint32_t so = sw_off(row, colByte);
            asm volatile("ldmatrix.sync.aligned.m8n8.x4.shared.b16 {%0,%1,%2,%3}, [%4];"
                : "=r"(fa[buf][0][0]), "=r"(fa[buf][0][1]),
                  "=r"(fa[buf][0][2]), "=r"(fa[buf][0][3])
                : "r"(base + sub + so));
            asm volatile("ldmatrix.sync.aligned.m8n8.x4.shared.b16 {%0,%1,%2,%3}, [%4];"
                : "=r"(fa[buf][1][0]), "=r"(fa[buf][1][1]),
                  "=r"(fa[buf][1][2]), "=r"(fa[buf][1][3])
                : "r"(base + A_LO_OFF + sub + so));
        }
        #pragma unroll
        for (int nh = 0; nh < 2; nh++) {
            const uint32_t sub = (uint32_t)(kf >> 2) * 8192;   // B half-tiles 8K
            int krow = kfl * 16 + (lane & 7) + ((lane >> 3) & 1) * 8;
            int colByte = (warpN * 32 + nh * 16 + (lane >> 4) * 8) * 2;
            asm volatile("ldmatrix.sync.aligned.m8n8.x4.trans.shared.b16 {%0,%1,%2,%3}, [%4];"
                : "=r"(fb[buf][nh][0]), "=r"(fb[buf][nh][1]),
                  "=r"(fb[buf][nh][2]), "=r"(fb[buf][nh][3])
                : "r"(base + B_OFF + sub + sw_off(krow, colByte)));
        }
    };

    ld(0, 0);
    #pragma unroll
    for (int kf = 0; kf < NKF; kf++) {
        const int cur = kf & 1;
        if (kf + 1 < NKF) ld(kf + 1, cur ^ 1);     // prefetch next slice's frags
        #pragma unroll
        for (int j = 0; j < 4; j++) {
            uint32_t b0 = fb[cur][j >> 1][(j & 1) * 2];
            uint32_t b1 = fb[cur][j >> 1][(j & 1) * 2 + 1];
            asm volatile(
                "mma.sync.aligned.m16n8k16.row.col.f32.f16.f16.f32 "
                "{%0,%1,%2,%3}, {%4,%5,%6,%7}, {%8,%9}, {%0,%1,%2,%3};"
                : "+f"(acch[j][0]), "+f"(acch[j][1]), "+f"(acch[j][2]), "+f"(acch[j][3])
                : "r"(fa[cur][0][0]), "r"(fa[cur][0][1]),
                  "r"(fa[cur][0][2]), "r"(fa[cur][0][3]), "r"(b0), "r"(b1));
            asm volatile(
                "mma.sync.aligned.m16n8k16.row.col.f32.f16.f16.f32 "
                "{%0,%1,%2,%3}, {%4,%5,%6,%7}, {%8,%9}, {%0,%1,%2,%3};"
                : "+f"(accl[j][0]), "+f"(accl[j][1]), "+f"(accl[j][2]), "+f"(accl[j][3])
                : "r"(fa[cur][1][0]), "r"(fa[cur][1][1]),
                  "r"(fa[cur][1][2]), "r"(fa[cur][1][3]), "r"(b0), "r"(b1));
        }
    }
}

__global__ __launch_bounds__(128) void step_kernel(
    const __grid_constant__ TMaps tm, int t) {
    extern __shared__ __align__(1024) char smem[];
    __shared__ __align__(8) uint64_t s_mbar[NSLOT + 1];   // slots + state

    const int tid  = threadIdx.x;
    const int lane = tid & 31;
    const int warp = tid >> 5;
    const int warpM = warp & 1;     // 2 warps along M (16 rows each)
    const int warpN = warp >> 1;    // 2 warps along N (32 cols each)
    const int rowBase = blockIdx.y * 32;
    const int colBase = blockIdx.x * 64;
    const int pp = t & 1;

    const uint32_t smem_u32 = (uint32_t)__cvta_generic_to_shared(smem);
    const uint32_t mbar0    = (uint32_t)__cvta_generic_to_shared(s_mbar);

    const CUtensorMap* mShi = &tm.shi[pp];
    const CUtensorMap* mSlo = &tm.slo[pp];

    if (tid == 0) {
        #pragma unroll
        for (int s = 0; s < NSLOT + 1; s++) MBARRIER_INIT(mbar0 + s * 8, 1);
    }
    __syncthreads();

    auto issue = [&](int kk) {
        uint32_t base = smem_u32 + (kk % NSLOT) * STAGE_BYTES;
        uint32_t mb   = mbar0 + (kk % NSLOT) * 8;
        if (kk < 8) {
            int k0 = kk << 7;
            MBARRIER_EXPECT_TX(mb, 32768u);
            tma2d(base,                   mShi, k0,      rowBase, mb);
            tma2d(base + 4096,            mShi, k0 + 64, rowBase, mb);
            tma2d(base + A_LO_OFF,        mSlo, k0,      rowBase, mb);
            tma2d(base + A_LO_OFF + 4096, mSlo, k0 + 64, rowBase, mb);
            tma2d(base + B_OFF,           &tm.w, colBase, k0,      mb);
            tma2d(base + B_OFF + 8192,    &tm.w, colBase, k0 + 64, mb);
        } else {
            MBARRIER_EXPECT_TX(mb, 16384u);
            tma3d(base,            &tm.xhi, 0, t, rowBase, mb);
            tma3d(base + A_LO_OFF, &tm.xlo, 0, t, rowBase, mb);
            tma2d(base + B_OFF,    &tm.win, colBase, 0, mb);
        }
    };

    if (tid == 0) {
        // state tile prefetch (overlaps the whole GEMM)
        MBARRIER_EXPECT_TX(mbar0 + NSLOT * 8, 8192u);
        tma2d(smem_u32 + ST_OFF, &tm.st, colBase, rowBase, mbar0 + NSLOT * 8);
        issue(0); issue(1);
    }

    float acch[4][4], accl[4][4];
    #pragma unroll
    for (int j = 0; j < 4; j++)
        #pragma unroll
        for (int q = 0; q < 4; q++) { acch[j][q] = 0.0f; accl[j][q] = 0.0f; }

    for (int kk = 0; kk < NIT; kk++) {
        __syncthreads();             // all warps done reading slot (kk+2)%NSLOT
        if (tid == 0 && kk + 2 < NIT) issue(kk + 2);
        MBARRIER_WAIT_PARITY(mbar0 + (kk % NSLOT) * 8, (uint32_t)((kk / NSLOT) & 1));

        uint32_t base = smem_u32 + (kk % NSLOT) * STAGE_BYTES;
        if (kk < 8) do_block<8>(base, lane, warpM, warpN, acch, accl);
        else        do_block<4>(base, lane, warpM, warpN, acch, accl);
    }

    // ---- epilogue: combine hi/lo, leaky tanh; state read from smem copy,
    //      write fp32 state + fp16 hi/lo for next step ----
    MBARRIER_WAIT_PARITY(mbar0 + NSLOT * 8, 0u);
    __half* __restrict__ shiN = g_shi[pp ^ 1];
    __half* __restrict__ sloN = g_slo[pp ^ 1];
    #pragma unroll
    for (int j = 0; j < 4; j++)
        #pragma unroll
        for (int h = 0; h < 2; h++) {
            int rloc = warpM * 16 + (lane >> 2) + 8 * h;          // 0..31
            int cloc = warpN * 32 + j * 8 + (lane & 3) * 2;       // 0..62
            int row = rowBase + rloc;
            int col = colBase + cloc;
            long long idx = (long long)row * RES + col;
            float y0 = acch[j][h * 2 + 0] + accl[j][h * 2 + 0];
            float y1 = acch[j][h * 2 + 1] + accl[j][h * 2 + 1];
            float2 sold = *reinterpret_cast<float2*>(
                smem + ST_OFF + rloc * 256 + cloc * 4);
            float n0 = 0.5f * sold.x + 0.5f * fast_tanhf(y0);
            float n1 = 0.5f * sold.y + 0.5f * fast_tanhf(y1);
            *reinterpret_cast<float2*>(&g_state[idx]) = make_float2(n0, n1);
            __half h0 = __float2half(n0);
            __half h1 = __float2half(n1);
            __half2 hv; hv.x = h0; hv.y = h1;
            __half2 lv;
            lv.x = __float2half(n0 - __half2float(h0));
            lv.y = __float2half(n1 - __half2float(h1));
            *reinterpret_cast<__half2*>(&shiN[idx]) = hv;
            *reinterpret_cast<__half2*>(&sloN[idx]) = lv;
        }
}

// ---------------- output GEMM ----------------------------------------------
__global__ __launch_bounds__(64) void output_kernel(
    const float* __restrict__ Wout, float* __restrict__ out) {
    __shared__ float srow[RES];
    const int b = blockIdx.x;
    const int j = threadIdx.x;
    for (int k = j; k < RES; k += 64) srow[k] = g_state[b * RES + k];
    __syncthreads();
    float sum = 0.0f;
    #pragma unroll 8
    for (int k = 0; k < RES; k++)
        sum = fmaf(srow[k], Wout[k * OUTSZ + j], sum);
    out[b * OUTSZ + j] = sum;
}

// ---------------- host: tensormap construction ------------------------------
typedef CUresult (*EncodeFn)(CUtensorMap*, CUtensorMapDataType, cuuint32_t, void*,
                             const cuuint64_t*, const cuuint64_t*, const cuuint32_t*,
                             const cuuint32_t*, CUtensorMapInterleave, CUtensorMapSwizzle,
                             CUtensorMapL2promotion, CUtensorMapFloatOOBfill);

static EncodeFn get_encode_fn() {
    void* p = nullptr;
#if CUDART_VERSION >= 12050
    cudaDriverEntryPointQueryResult st;
    cudaGetDriverEntryPointByVersion("cuTensorMapEncodeTiled", &p, 12000,
                                     cudaEnableDefault, &st);
#else
    cudaDriverEntryPointQueryResult st;
    cudaGetDriverEntryPoint("cuTensorMapEncodeTiled", &p, cudaEnableDefault, &st);
#endif
    return (EncodeFn)p;
}

static void enc2d_box(EncodeFn f, CUtensorMap* m, void* ptr,
                      uint64_t d0, uint64_t d1, uint64_t stride1B,
                      uint32_t b0, uint32_t b1) {
    cuuint64_t dims[2] = {d0, d1};
    cuuint64_t strides[1] = {stride1B};
    cuuint32_t box[2] = {b0, b1};
    cuuint32_t es[2] = {1, 1};
    f(m, CU_TENSOR_MAP_DATA_TYPE_FLOAT16, 2, ptr, dims, strides, box, es,
      CU_TENSOR_MAP_INTERLEAVE_NONE, CU_TENSOR_MAP_SWIZZLE_128B,
      CU_TENSOR_MAP_L2_PROMOTION_L2_128B, CU_TENSOR_MAP_FLOAT_OOB_FILL_NONE);
}

static void enc_state(EncodeFn f, CUtensorMap* m, void* ptr) {
    cuuint64_t dims[2] = {RES, BATCH};
    cuuint64_t strides[1] = {RES * 4ull};
    cuuint32_t box[2] = {64, 32};
    cuuint32_t es[2] = {1, 1};
    f(m, CU_TENSOR_MAP_DATA_TYPE_FLOAT32, 2, ptr, dims, strides, box, es,
      CU_TENSOR_MAP_INTERLEAVE_NONE, CU_TENSOR_MAP_SWIZZLE_NONE,
      CU_TENSOR_MAP_L2_PROMOTION_L2_128B, CU_TENSOR_MAP_FLOAT_OOB_FILL_NONE);
}

static void enc3d_x(EncodeFn f, CUtensorMap* m, void* ptr) {
    cuuint64_t dims[3] = {INSZ, SEQLEN, BATCH};
    cuuint64_t strides[2] = {INSZ * 2ull, (uint64_t)SEQLEN * INSZ * 2ull};
    cuuint32_t box[3] = {64, 1, 32};
    cuuint32_t es[3] = {1, 1, 1};
    f(m, CU_TENSOR_MAP_DATA_TYPE_FLOAT16, 3, ptr, dims, strides, box, es,
      CU_TENSOR_MAP_INTERLEAVE_NONE, CU_TENSOR_MAP_SWIZZLE_128B,
      CU_TENSOR_MAP_L2_PROMOTION_L2_128B, CU_TENSOR_MAP_FLOAT_OOB_FILL_NONE);
}

// ---------------- launch ----------------------------------------------------
extern "C" void kernel_launch(void* const* d_in, const int* in_sizes, int n_in,
                              void* d_out, int out_size) {
    const float* input = (const float*)d_in[0];   // [512,512,64]
    const float* Wres  = (const float*)d_in[1];   // [1024,1024]
    const float* Win   = (const float*)d_in[2];   // [64,1024]
    const float* Wout  = (const float*)d_in[3];   // [1024,64]
    float* out = (float*)d_out;

    void *state, *shi, *slo, *w16, *win16, *xhi, *xlo;
    cudaGetSymbolAddress(&state, g_state);
    cudaGetSymbolAddress(&shi,   g_shi);
    cudaGetSymbolAddress(&slo,   g_slo);
    cudaGetSymbolAddress(&w16,   g_w16);
    cudaGetSymbolAddress(&win16, g_win16);
    cudaGetSymbolAddress(&xhi,   g_xhi);
    cudaGetSymbolAddress(&xlo,   g_xlo);

    EncodeFn enc = get_encode_fn();
    TMaps tm;
    enc2d_box(enc, &tm.shi[0], shi, RES, BATCH, RES * 2ull, 64, 32);
    enc2d_box(enc, &tm.shi[1], (char*)shi + (size_t)BATCH * RES * 2,
              RES, BATCH, RES * 2ull, 64, 32);
    enc2d_box(enc, &tm.slo[0], slo, RES, BATCH, RES * 2ull, 64, 32);
    enc2d_box(enc, &tm.slo[1], (char*)slo + (size_t)BATCH * RES * 2,
              RES, BATCH, RES * 2ull, 64, 32);
    enc2d_box(enc, &tm.w, w16, RES, RES, RES * 2ull, 64, 64);
    enc2d_box(enc, &tm.win, win16, RES, INSZ, RES * 2ull, 64, 64);
    enc3d_x(enc, &tm.xhi, xhi);
    enc3d_x(enc, &tm.xlo, xlo);
    enc_state(enc, &tm.st, state);

    cudaFuncSetAttribute(step_kernel,
                         cudaFuncAttributeMaxDynamicSharedMemorySize,
                         SMEM_TOTAL);

    prep_kernel<<<4096, 256>>>(input, Wres, Win);

    dim3 grid(RES / 64, BATCH / 32);   // (16, 16) = 256 CTAs, ~2 per SM
    for (int t = 0; t < SEQLEN; t++)
        step_kernel<<<grid, 128, SMEM_TOTAL>>>(tm, t);

    output_kernel<<<BATCH, 64>>>(Wout, out);
}